// round 16
// baseline (speedup 1.0000x reference)
#include <cuda_runtime.h>
#include <stdint.h>

// Problem constants
#define NBINS      32
#define NCH        64            // B*C = 8*8
#define HW         65536         // 256*256 pixels per channel
#define NSUB       256           // fine histogram sub-bins over [0,1)
#define CTAS_PER_CH 8
#define NCTA      (NCH * CTAS_PER_CH)       // 512
#define F4_PER_CTA ((HW / 4) / CTAS_PER_CH) // 2048 float4 per CTA
#define NTHR       128           // threads per CTA
#define PAD        32            // +-4 sigma = +-32 sub-bins (sigma = 8 sub)
#define WIN        (2 * PAD)     // 64
#define NSTEP      (WIN / 32)    // 2 strided warp steps

#define AMPL   0.3989472f        // ER/RATIO = 1/2.5066
#define INV31  (1.0f / 31.0f)    // bin spacing (linspace(0,1,32))
#define K512   512.0f            // 1/(2*sigma^2), sigma = 1/32
#define DELTA  (1.0f / 256.0f)   // sub-bin width
#define STEP32 (32.0f * DELTA)   // lane stride in x (= 4 sigma)

// ---------------------------------------------------------------------------
// Kernel 0: zero the output (stream order: completes before fused kernel).
// ---------------------------------------------------------------------------
__global__ void zero_kernel(float* __restrict__ out)
{
    out[blockIdx.x * 1024 + threadIdx.x] = 0.0f;
}

// ---------------------------------------------------------------------------
// Fused kernel: one CTA per slab (1/8 channel, 8192 pixels), 128 threads.
//
// Phase 1 — ZERO-ATOMIC thread-private byte histogram.
//   Table hs[bin][128] (u8). Slot for thread t, bin b:
//     byte = b*128 + lane*4 + warpid   (lane = t&31, warpid = t>>5)
//   -> word index = b*32 + lane  => bank == lane for EVERY lane, ANY bin:
//      guaranteed conflict-free; the 4 warps use the 4 bytes of the word
//      (byte stores never collide). Each slot is written by exactly ONE
//      thread -> plain LDS.U8 + IADD + STS.U8, no atomics at all.
//      Max count/slot = 64 pixels/thread <= 255: no overflow.
//   Replaces the ~2 cyc/lane ATOMS backbone (~8.8us) with 2 LSU warp-ops
//   at the 2-cyc issue floor.
// Phase 2 — thread t sums bins {t, t+128}: 32 words each, lane-staggered
//   (conflict-free) LDS + __dp4a byte-sum -> +-PAD zero-padded float array.
// Phase 3 — warp-per-bin Gaussian window (8 bins per warp), 2 steps of 32
//   sub-bins, lattice recurrence (2 expf per bin-lane); lane0 fire-and-
//   forget RED.ADDs into out. No fences, no counters, no blocking atomics.
// ---------------------------------------------------------------------------
__global__ __launch_bounds__(NTHR, 6)
void fused_kernel(const float* __restrict__ x, float* __restrict__ out)
{
    __shared__ unsigned char hs[NSUB * NTHR];   // 32 KB thread-private counts
    __shared__ float         hf[NSUB + WIN];    // 1.25 KB padded floats

    const int tid  = threadIdx.x;
    const int warp = tid >> 5;
    const int lane = tid & 31;

    // zero the table (2048 uint4 = 16 per thread)
    uint4* __restrict__ hw4 = reinterpret_cast<uint4*>(hs);
    #pragma unroll
    for (int i = tid; i < (NSUB * NTHR) / 16; i += NTHR)
        hw4[i] = make_uint4(0u, 0u, 0u, 0u);
    __syncthreads();

    // ---- Phase 1: thread-private histogram (no atomics) -------------------
    const float4* __restrict__ p =
        reinterpret_cast<const float4*>(x) + (size_t)blockIdx.x * F4_PER_CTA;

    const int base = (lane << 2) | warp;    // byte offset within a bin row

    #pragma unroll 4
    for (int i = tid; i < F4_PER_CTA; i += NTHR) {
        float4 v = p[i];
        int i0 = ((int)(v.x * (float)NSUB) << 7) + base;
        int i1 = ((int)(v.y * (float)NSUB) << 7) + base;
        int i2 = ((int)(v.z * (float)NSUB) << 7) + base;
        int i3 = ((int)(v.w * (float)NSUB) << 7) + base;
        hs[i0]++;
        hs[i1]++;
        hs[i2]++;
        hs[i3]++;
    }
    __syncthreads();

    // ---- Phase 2: sum 128 thread slots per bin via dp4a -------------------
    // thread t owns bins t and t+128; words of bin b at b*32 + k, read
    // staggered k = (kk + lane) & 31 -> bank (kk+lane)&31: conflict-free.
    const unsigned int* __restrict__ hw =
        reinterpret_cast<const unsigned int*>(hs);
    #pragma unroll
    for (int bb = 0; bb < 2; bb++) {
        const int b = tid + bb * NTHR;
        unsigned int s = 0u;
        #pragma unroll
        for (int kk = 0; kk < 32; kk++)
            s = __dp4a(hw[(b << 5) + ((kk + lane) & 31)], 0x01010101u, s);
        hf[PAD + b] = (float)s;
    }
    if (tid < PAD) {
        hf[tid] = 0.0f;
        hf[PAD + NSUB + tid] = 0.0f;
    }
    __syncthreads();

    // ---- Phase 3: warp-per-bin convolution (8 bins per warp) --------------
    const int ch = blockIdx.x >> 3;
    const float gS = __expf(-2.0f * K512 * STEP32 * STEP32);

    #pragma unroll
    for (int b = 0; b < 8; b++) {
        const int j = warp + 4 * b;                 // bin 0..31
        const float cj = (float)j * INV31;
        const int icenter = (int)(cj * (float)NSUB);
        const float d0 = ((float)(icenter - PAD + lane) + 0.5f) * DELTA - cj;

        float w = __expf(-d0 * d0 * K512);
        float r = __expf(-K512 * STEP32 * (2.0f * d0 + STEP32));

        int idx = icenter + lane;                   // = PAD + m0 + lane
        float acc = 0.0f;
        #pragma unroll
        for (int i = 0; i < NSTEP; i++) {
            acc = fmaf(hf[idx], w, acc);
            w *= r;
            r *= gS;
            idx += 32;
        }

        // full-warp reduce
        #pragma unroll
        for (int off = 16; off > 0; off >>= 1)
            acc += __shfl_down_sync(0xFFFFFFFFu, acc, off);

        if (lane == 0)
            atomicAdd(&out[ch * NBINS + j], acc * AMPL);  // RED, no return
    }
}

// ---------------------------------------------------------------------------
extern "C" void kernel_launch(void* const* d_in, const int* in_sizes, int n_in,
                              void* d_out, int out_size)
{
    const float* x = (const float*)d_in[0];   // [8,8,256,256] fp32
    float* out = (float*)d_out;               // [8,256,1,1] = 2048 fp32

    zero_kernel<<<2, 1024>>>(out);
    fused_kernel<<<NCTA, NTHR>>>(x, out);
}